// round 6
// baseline (speedup 1.0000x reference)
#include <cuda_runtime.h>
#include <cuda_bf16.h>
#include <cstdint>

// Device-global scratch (no allocations allowed). Zero-initialized at load;
// the last block resets them to zero so every graph replay sees the same state.
__device__ double        g_acc       = 0.0;
__device__ unsigned int  g_acc_count = 0;

#define LOG2E 1.44269504088896340736f
#define LN2   0.69314718055994530942f

__device__ __forceinline__ float rcp_approx(float x) {
    float r; asm("rcp.approx.f32 %0, %1;" : "=f"(r) : "f"(x)); return r;
}
__device__ __forceinline__ float ex2_approx(float x) {
    float r; asm("ex2.approx.f32 %0, %1;" : "=f"(r) : "f"(x)); return r;
}
__device__ __forceinline__ float lg2_approx(float x) {
    float r; asm("lg2.approx.f32 %0, %1;" : "=f"(r) : "f"(x)); return r;
}

// tbl[p*3+t] = { 1.5*P[p][t],  0.1*(p!=t),  class_w[t]*ln2,  0 }
__device__ __forceinline__ void row_loss(float l0, float l1, float l2, int t,
                                         const float4* __restrict__ tbl,
                                         float& acc)
{
    // exact first-occurrence argmax (strict > matches jnp.argmax)
    const bool  pa  = (l1 > l0);
    const float m01 = fmaxf(l0, l1);
    const bool  pb  = (l2 > m01);
    const float m   = fmaxf(m01, l2);

    const int p3  = pb ? 6 : (pa ? 3 : 0);     // p * 3
    const float4 e = tbl[p3 + t];              // {pen15, confw, aln2, -}

    // log2-domain shifted deltas; max lane is exactly 0 -> exp = 1
    const float nmK = -m * LOG2E;
    const float s0 = fmaf(l0, LOG2E, nmK);
    const float s1 = fmaf(l1, LOG2E, nmK);
    const float s2 = fmaf(l2, LOG2E, nmK);

    const float e0 = ex2_approx(s0);
    const float e1 = ex2_approx(s1);
    const float e2 = ex2_approx(s2);
    const float S    = e0 + e1 + e2;
    const float rcpS = rcp_approx(S);          // == max prob (exp at argmax is 1)
    const float lg2S = lg2_approx(S);

    const float st = (t == 0) ? s0 : ((t == 1) ? s1 : s2);
    const float et = (t == 0) ? e0 : ((t == 1) ? e1 : e2);

    const float pt  = et * rcpS;               // prob[target]
    const float omp = 1.0f - pt;
    const float ce2 = lg2S - st;               // ce / ln2

    acc = fmaf(e.z * omp * omp, ce2, acc);     // alpha*ln2 * focal * (ce/ln2)
    acc += e.x;                                // 1.5 * penalty
    acc = fmaf(e.y, rcpS, acc);                // 0.1 * (p!=t) * max_prob
}

__global__ void __launch_bounds__(256)
trading_loss_kernel(const float* __restrict__ logits,
                    const int*   __restrict__ targets,
                    const float* __restrict__ class_w,
                    float*       __restrict__ out,
                    int ngroups, float inv_n, int nblocks)
{
    __shared__ float4 tbl[9];
    __shared__ float  warp_sums[8];
    __shared__ bool   is_last;

    if (threadIdx.x < 9) {
        const int p = threadIdx.x / 3;
        const int t = threadIdx.x - p * 3;
        int d = p - t; d = (d < 0) ? -d : d;
        const float pen15 = 0.75f * (float)d + ((d == 2) ? 0.75f : 0.0f);
        const float confw = (d != 0) ? 0.1f : 0.0f;
        tbl[threadIdx.x] = make_float4(pen15, confw, class_w[t] * LN2, 0.0f);
    }
    __syncthreads();

    float acc = 0.0f;

    const int tid    = blockIdx.x * blockDim.x + threadIdx.x;
    const int stride = gridDim.x * blockDim.x;

    // counted loop with rolling pointers (no per-iter bounds compare,
    // no per-iter index*48 multiply)
    int n_iter = 0;
    if (tid < ngroups) n_iter = 1 + (ngroups - 1 - tid) / stride;

    const float4* lp = reinterpret_cast<const float4*>(logits) + (size_t)tid * 3;
    const int4*   tp = reinterpret_cast<const int4*>(targets) + tid;
    const size_t  lstep = (size_t)stride * 3;

    #pragma unroll 2
    for (int i = 0; i < n_iter; ++i) {
        const float4 a0 = __ldg(lp + 0);
        const float4 a1 = __ldg(lp + 1);
        const float4 a2 = __ldg(lp + 2);
        const int4   t4 = __ldg(tp);
        lp += lstep;
        tp += stride;

        row_loss(a0.x, a0.y, a0.z, t4.x, tbl, acc);
        row_loss(a0.w, a1.x, a1.y, t4.y, tbl, acc);
        row_loss(a1.z, a1.w, a2.x, t4.z, tbl, acc);
        row_loss(a2.y, a2.z, a2.w, t4.w, tbl, acc);
    }

    // ---- block reduction ----
    #pragma unroll
    for (int off = 16; off > 0; off >>= 1)
        acc += __shfl_xor_sync(0xFFFFFFFFu, acc, off);

    const int lane = threadIdx.x & 31;
    const int wid  = threadIdx.x >> 5;
    if (lane == 0) warp_sums[wid] = acc;
    __syncthreads();

    if (wid == 0) {
        float v = (lane < (blockDim.x >> 5)) ? warp_sums[lane] : 0.0f;
        #pragma unroll
        for (int off = 4; off > 0; off >>= 1)
            v += __shfl_xor_sync(0xFFFFFFFFu, v, off);
        if (lane == 0) {
            atomicAdd(&g_acc, (double)v);
            __threadfence();
            unsigned int ticket = atomicAdd(&g_acc_count, 1u);
            is_last = (ticket == (unsigned int)nblocks - 1u);
        }
    }
    __syncthreads();

    if (is_last && threadIdx.x == 0) {
        double total = g_acc;
        out[0] = (float)(total * (double)inv_n);
        g_acc = 0.0;
        g_acc_count = 0u;
    }
}

extern "C" void kernel_launch(void* const* d_in, const int* in_sizes, int n_in,
                              void* d_out, int out_size)
{
    const float* logits  = (const float*)d_in[0];
    const int*   targets = (const int*)d_in[1];
    const float* class_w = (const float*)d_in[2];
    float*       out     = (float*)d_out;

    const int batch   = in_sizes[1];       // targets element count = B
    const int ngroups = batch / 4;         // 4 rows per float4-group

    const int threads = 256;
    int blocks = 152 * 6;                  // single resident wave on GB300 (152 SMs)
    int maxb   = (ngroups + threads - 1) / threads;
    if (blocks > maxb) blocks = maxb;
    if (blocks < 1) blocks = 1;

    trading_loss_kernel<<<blocks, threads>>>(logits, targets, class_w, out,
                                             ngroups, 1.0f / (float)batch, blocks);
}

// round 7
// speedup vs baseline: 1.1977x; 1.1977x over previous
#include <cuda_runtime.h>
#include <cuda_bf16.h>
#include <cstdint>

// Device-global scratch (no allocations allowed). Zero-initialized at load;
// the last block resets them to zero so every graph replay sees the same state.
__device__ double        g_acc       = 0.0;
__device__ unsigned int  g_acc_count = 0;

#define LOG2E 1.44269504088896340736f
#define LN2   0.69314718055994530942f

__device__ __forceinline__ float rcp_approx(float x) {
    float r; asm("rcp.approx.f32 %0, %1;" : "=f"(r) : "f"(x)); return r;
}
__device__ __forceinline__ float ex2_approx(float x) {
    float r; asm("ex2.approx.f32 %0, %1;" : "=f"(r) : "f"(x)); return r;
}
__device__ __forceinline__ float lg2_approx(float x) {
    float r; asm("lg2.approx.f32 %0, %1;" : "=f"(r) : "f"(x)); return r;
}

// tbl[p*3+t] = { 1.5*P[p][t],  0.1*(p!=t),  class_w[t]*ln2,  0 }
__device__ __forceinline__ void row_loss(float l0, float l1, float l2, int t,
                                         const float4* __restrict__ tbl,
                                         float& acc)
{
    // exact first-occurrence argmax (strict > matches jnp.argmax)
    const bool  pa  = (l1 > l0);
    const float m01 = fmaxf(l0, l1);
    const bool  pb  = (l2 > m01);
    const float m   = fmaxf(m01, l2);

    const int p3  = pb ? 6 : (pa ? 3 : 0);     // p * 3
    const float4 e = tbl[p3 + t];              // {pen15, confw, aln2, -}

    // log2-domain shifted deltas; max lane is exactly 0 -> exp = 1
    const float nmK = -m * LOG2E;
    const float s0 = fmaf(l0, LOG2E, nmK);
    const float s1 = fmaf(l1, LOG2E, nmK);
    const float s2 = fmaf(l2, LOG2E, nmK);

    const float e0 = ex2_approx(s0);
    const float e1 = ex2_approx(s1);
    const float e2 = ex2_approx(s2);
    const float S    = e0 + e1 + e2;
    const float rcpS = rcp_approx(S);          // == max prob (exp at argmax is 1)
    const float lg2S = lg2_approx(S);

    const float st = (t == 0) ? s0 : ((t == 1) ? s1 : s2);
    const float et = (t == 0) ? e0 : ((t == 1) ? e1 : e2);

    const float pt  = et * rcpS;               // prob[target]
    const float omp = 1.0f - pt;
    const float ce2 = lg2S - st;               // ce / ln2

    acc = fmaf(e.z * omp * omp, ce2, acc);     // alpha*ln2 * focal * (ce/ln2)
    acc += e.x;                                // 1.5 * penalty
    acc = fmaf(e.y, rcpS, acc);                // 0.1 * (p!=t) * max_prob
}

__global__ void __launch_bounds__(256, 5)
trading_loss_kernel(const float* __restrict__ logits,
                    const int*   __restrict__ targets,
                    const float* __restrict__ class_w,
                    float*       __restrict__ out,
                    int ngroups, float inv_n, int nblocks)
{
    __shared__ float4 tbl[9];
    __shared__ float  warp_sums[8];
    __shared__ bool   is_last;

    if (threadIdx.x < 9) {
        const int p = threadIdx.x / 3;
        const int t = threadIdx.x - p * 3;
        int d = p - t; d = (d < 0) ? -d : d;
        const float pen15 = 0.75f * (float)d + ((d == 2) ? 0.75f : 0.0f);
        const float confw = (d != 0) ? 0.1f : 0.0f;
        tbl[threadIdx.x] = make_float4(pen15, confw, class_w[t] * LN2, 0.0f);
    }
    __syncthreads();

    float acc = 0.0f;

    const int tid    = blockIdx.x * blockDim.x + threadIdx.x;
    const int stride = gridDim.x * blockDim.x;

    const float4* lbase = reinterpret_cast<const float4*>(logits);
    const int4*   tbase = reinterpret_cast<const int4*>(targets);

    const int n_iter = (tid < ngroups) ? (1 + (ngroups - 1 - tid) / stride) : 0;

    if (n_iter > 0) {
        // prologue: load first group
        int g = tid;
        float4 a0 = __ldg(lbase + (size_t)g * 3 + 0);
        float4 a1 = __ldg(lbase + (size_t)g * 3 + 1);
        float4 a2 = __ldg(lbase + (size_t)g * 3 + 2);
        int4   t4 = __ldg(tbase + g);

        // steady state: prefetch next group's loads BEFORE computing current
        for (int i = 1; i < n_iter; ++i) {
            g += stride;
            const float4 b0 = __ldg(lbase + (size_t)g * 3 + 0);
            const float4 b1 = __ldg(lbase + (size_t)g * 3 + 1);
            const float4 b2 = __ldg(lbase + (size_t)g * 3 + 2);
            const int4   u4 = __ldg(tbase + g);

            row_loss(a0.x, a0.y, a0.z, t4.x, tbl, acc);
            row_loss(a0.w, a1.x, a1.y, t4.y, tbl, acc);
            row_loss(a1.z, a1.w, a2.x, t4.z, tbl, acc);
            row_loss(a2.y, a2.z, a2.w, t4.w, tbl, acc);

            a0 = b0; a1 = b1; a2 = b2; t4 = u4;
        }

        // epilogue: compute last group
        row_loss(a0.x, a0.y, a0.z, t4.x, tbl, acc);
        row_loss(a0.w, a1.x, a1.y, t4.y, tbl, acc);
        row_loss(a1.z, a1.w, a2.x, t4.z, tbl, acc);
        row_loss(a2.y, a2.z, a2.w, t4.w, tbl, acc);
    }

    // ---- block reduction ----
    #pragma unroll
    for (int off = 16; off > 0; off >>= 1)
        acc += __shfl_xor_sync(0xFFFFFFFFu, acc, off);

    const int lane = threadIdx.x & 31;
    const int wid  = threadIdx.x >> 5;
    if (lane == 0) warp_sums[wid] = acc;
    __syncthreads();

    if (wid == 0) {
        float v = (lane < (blockDim.x >> 5)) ? warp_sums[lane] : 0.0f;
        #pragma unroll
        for (int off = 4; off > 0; off >>= 1)
            v += __shfl_xor_sync(0xFFFFFFFFu, v, off);
        if (lane == 0) {
            atomicAdd(&g_acc, (double)v);
            __threadfence();
            unsigned int ticket = atomicAdd(&g_acc_count, 1u);
            is_last = (ticket == (unsigned int)nblocks - 1u);
        }
    }
    __syncthreads();

    if (is_last && threadIdx.x == 0) {
        double total = g_acc;
        out[0] = (float)(total * (double)inv_n);
        g_acc = 0.0;
        g_acc_count = 0u;
    }
}

extern "C" void kernel_launch(void* const* d_in, const int* in_sizes, int n_in,
                              void* d_out, int out_size)
{
    const float* logits  = (const float*)d_in[0];
    const int*   targets = (const int*)d_in[1];
    const float* class_w = (const float*)d_in[2];
    float*       out     = (float*)d_out;

    const int batch   = in_sizes[1];       // targets element count = B
    const int ngroups = batch / 4;         // 4 rows per float4-group

    const int threads = 256;
    int blocks = 152 * 5;                  // single resident wave at 5 blocks/SM
    int maxb   = (ngroups + threads - 1) / threads;
    if (blocks > maxb) blocks = maxb;
    if (blocks < 1) blocks = 1;

    trading_loss_kernel<<<blocks, threads>>>(logits, targets, class_w, out,
                                             ngroups, 1.0f / (float)batch, blocks);
}